// round 6
// baseline (speedup 1.0000x reference)
#include <cuda_runtime.h>
#include <cstdint>

#define BB 64
#define SS 14
#define NSP (SS*SS)      // 196
#define CC 32
#define NN (NSP*CC)      // 6272
#define OO 10
#define HH 16
#define EPSV 1e-9f
#define NBLK 25          // 25*256 = 6400 >= 6272
#define NW 8             // warps per block

typedef unsigned long long u64;

// Scratch
__device__ float g_partials[BB * OO * NBLK * 36]; // 0..15 S1[perm], 16..31 S2[perm], 32 S0
__device__ float g_params[BB * OO * 40];          // 0..15 c1[ip], 16..31 hv[ip], 32 c0

// ---- f32x2 packed helpers ----
__device__ __forceinline__ u64 pk(float lo, float hi) {
    u64 r; asm("mov.b64 %0, {%1,%2};" : "=l"(r) : "f"(lo), "f"(hi)); return r;
}
__device__ __forceinline__ u64 pkd(float x) {  // duplicate broadcast pair
    u64 r; asm("mov.b64 %0, {%1,%1};" : "=l"(r) : "f"(x)); return r;
}
__device__ __forceinline__ void upk(u64 a, float& lo, float& hi) {
    asm("mov.b64 {%0,%1}, %2;" : "=f"(lo), "=f"(hi) : "l"(a));
}
__device__ __forceinline__ u64 f2fma(u64 a, u64 b, u64 c) {
    u64 d; asm("fma.rn.f32x2 %0, %1, %2, %3;" : "=l"(d) : "l"(a), "l"(b), "l"(c)); return d;
}
__device__ __forceinline__ u64 f2mul(u64 a, u64 b) {
    u64 d; asm("mul.rn.f32x2 %0, %1, %2;" : "=l"(d) : "l"(a), "l"(b)); return d;
}
__device__ __forceinline__ u64 f2add(u64 a, u64 b) {
    u64 d; asm("add.rn.f32x2 %0, %1, %2;" : "=l"(d) : "l"(a), "l"(b)); return d;
}

// Butterfly stages 8..1 on a 16-value distributed set.
__device__ __forceinline__ float bfly16_tail(float a16[16], int lane) {
    float a8[8];
#pragma unroll
    for (int i = 0; i < 8; i++) {
        float mine = (lane & 8) ? a16[i + 8] : a16[i];
        float give = (lane & 8) ? a16[i] : a16[i + 8];
        a8[i] = mine + __shfl_xor_sync(0xffffffffu, give, 8);
    }
    float a4[4];
#pragma unroll
    for (int i = 0; i < 4; i++) {
        float mine = (lane & 4) ? a8[i + 4] : a8[i];
        float give = (lane & 4) ? a8[i] : a8[i + 4];
        a4[i] = mine + __shfl_xor_sync(0xffffffffu, give, 4);
    }
    float a2[2];
#pragma unroll
    for (int i = 0; i < 2; i++) {
        float mine = (lane & 2) ? a4[i + 2] : a4[i];
        float give = (lane & 2) ? a4[i] : a4[i + 2];
        a2[i] = mine + __shfl_xor_sync(0xffffffffu, give, 2);
    }
    float mine = (lane & 1) ? a2[1] : a2[0];
    float give = (lane & 1) ? a2[0] : a2[1];
    return mine + __shfl_xor_sync(0xffffffffu, give, 1);
}

// Distributed reduce of 16 values over 32 lanes: lane L gets total of value (L>>1)&15.
__device__ __forceinline__ float bfly16_full(const float val[16], int lane) {
    float v8[8];
#pragma unroll
    for (int i = 0; i < 8; i++) {
        float mine = (lane & 16) ? val[i + 8] : val[i];
        float give = (lane & 16) ? val[i] : val[i + 8];
        v8[i] = mine + __shfl_xor_sync(0xffffffffu, give, 16);
    }
    float v4[4];
#pragma unroll
    for (int i = 0; i < 4; i++) {
        float mine = (lane & 8) ? v8[i + 4] : v8[i];
        float give = (lane & 8) ? v8[i] : v8[i + 4];
        v4[i] = mine + __shfl_xor_sync(0xffffffffu, give, 8);
    }
    float v2[2];
#pragma unroll
    for (int i = 0; i < 2; i++) {
        float mine = (lane & 4) ? v4[i + 2] : v4[i];
        float give = (lane & 4) ? v4[i] : v4[i + 2];
        v2[i] = mine + __shfl_xor_sync(0xffffffffu, give, 4);
    }
    float mine = (lane & 2) ? v2[1] : v2[0];
    float give = (lane & 2) ? v2[0] : v2[1];
    float v1 = mine + __shfl_xor_sync(0xffffffffu, give, 2);
    return v1 + __shfl_xor_sync(0xffffffffu, v1, 1);
}

template <bool FIRST>
__global__ void __launch_bounds__(256, 3) em_pass_kernel(const float* __restrict__ pose,
                                                         const float* __restrict__ act,
                                                         const float* __restrict__ w) {
    __shared__ __align__(16) float4 w_s4[OO * 4 * 32];  // [r=o*4+j][c], 20KB
    __shared__ __align__(16) float p_s[OO * 36];        // c1[16], hv[16], c0
    __shared__ float red_s[NW][OO][32];                 // 10KB
    __shared__ float red0_s[NW][16];                    // 0.5KB

    const int b = blockIdx.y, nb = blockIdx.x;
    const int tid = threadIdx.x, lane = tid & 31, wid = tid >> 5;

    // Stage w: global (c,o,j,k) float4 over k -> w_s4[(o*4+j)*32 + c]
    const float4* wg4 = reinterpret_cast<const float4*>(w);
    for (int idx = tid; idx < CC * 40; idx += 256) {
        int ci = idx / 40, r = idx % 40;  // r = o*4+j
        w_s4[r * 32 + ci] = wg4[idx];
    }
    if (!FIRST) {
        for (int idx = tid; idx < OO * 36; idx += 256) {
            int o = idx / 36, t = idx % 36;
            p_s[idx] = (t < 33) ? g_params[(b * OO + o) * 40 + t] : 0.f;
        }
    }
    __syncthreads();

    // Per-thread item
    const int n = nb * 256 + tid;
    const bool valid = n < NN;
    const int nn = valid ? n : (NN - 1);
    const int ns = nn >> 5, c = nn & 31;
    const float4* pp = reinterpret_cast<const float4*>(pose) +
                       (size_t)((b * NSP + ns) * CC + c) * 4;
    float4 R0 = pp[0], R1 = pp[1], R2 = pp[2], R3 = pp[3];
    const float a = valid ? act[(size_t)b * NN + n] : 0.f;
    const int s1 = ns / SS, s2 = ns % SS;
    const u64 cp0 = pk((s1 + 0.5f) * (1.f / SS), 0.f);
    const u64 cp1 = pk((s2 + 0.5f) * (1.f / SS), 0.f);

    // Pose pairs over i: P2[i2*4+j] = (P[i2][j], P[i2+2][j])
    u64 P2[8];
    P2[0] = pk(R0.x, R2.x); P2[1] = pk(R0.y, R2.y); P2[2] = pk(R0.z, R2.z); P2[3] = pk(R0.w, R2.w);
    P2[4] = pk(R1.x, R3.x); P2[5] = pk(R1.y, R3.y); P2[6] = pk(R1.z, R3.z); P2[7] = pk(R1.w, R3.w);

    // votes: v[q] = (vote[h=q], vote[h=q+8]),  q = i2*4+k
    auto votes = [&](int o, u64 v[8]) {
        const float4* wp = w_s4 + (o * 4) * 32 + c;
        {
            float4 W = wp[0];
            u64 w0 = pkd(W.x), w1 = pkd(W.y), w2 = pkd(W.z), w3 = pkd(W.w);
            v[0] = f2mul(P2[0], w0); v[1] = f2mul(P2[0], w1);
            v[2] = f2mul(P2[0], w2); v[3] = f2mul(P2[0], w3);
            v[4] = f2mul(P2[4], w0); v[5] = f2mul(P2[4], w1);
            v[6] = f2mul(P2[4], w2); v[7] = f2mul(P2[4], w3);
        }
#pragma unroll
        for (int j = 1; j < 4; j++) {
            float4 W = wp[j * 32];
            u64 w0 = pkd(W.x), w1 = pkd(W.y), w2 = pkd(W.z), w3 = pkd(W.w);
            v[0] = f2fma(P2[j], w0, v[0]); v[1] = f2fma(P2[j], w1, v[1]);
            v[2] = f2fma(P2[j], w2, v[2]); v[3] = f2fma(P2[j], w3, v[3]);
            v[4] = f2fma(P2[4 + j], w0, v[4]); v[5] = f2fma(P2[4 + j], w1, v[5]);
            v[6] = f2fma(P2[4 + j], w2, v[6]); v[7] = f2fma(P2[4 + j], w3, v[7]);
        }
        v[0] = f2add(v[0], cp0);  // coord r on h=0
        v[1] = f2add(v[1], cp1);  // coord c on h=1
    };

    float rp[OO];
    if (FIRST) {
#pragma unroll
        for (int o = 0; o < OO; o++) rp[o] = a * (1.f / OO);
    } else {
        // Pass A: la[o] = c0 - sum_h v*(hv*v + c1)
#pragma unroll 2
        for (int o = 0; o < OO; o++) {
            u64 v[8];
            votes(o, v);
            const u64* mp = reinterpret_cast<const u64*>(p_s + o * 36);
            u64 ap = 0;
#pragma unroll
            for (int q = 0; q < 8; q++) {
                u64 t = f2fma(mp[8 + q], v[q], mp[q]);  // hv*v + c1
                ap = f2fma(t, v[q], ap);
            }
            float l, h;
            upk(ap, l, h);
            rp[o] = p_s[o * 36 + 32] - (l + h);
        }
        // Softmax over o (registers)
        float mx = rp[0];
#pragma unroll
        for (int o = 1; o < OO; o++) mx = fmaxf(mx, rp[o]);
        float s = 0.f;
#pragma unroll
        for (int o = 0; o < OO; o++) {
            rp[o] = __expf(rp[o] - mx);
            s += rp[o];
        }
        float sc = a / s;
#pragma unroll
        for (int o = 0; o < OO; o++) rp[o] *= sc;
    }

    // Pass B: weighted moments; stage-16 butterfly fused (S1 pair <-> S2 pair)
#pragma unroll 2
    for (int o = 0; o < OO; o++) {
        u64 v[8];
        votes(o, v);
        u64 rpp = pkd(rp[o]);
        float a16[16];
#pragma unroll
        for (int q = 0; q < 8; q++) {
            u64 t1 = f2mul(rpp, v[q]);   // (S1[q], S1[q+8])
            u64 t2 = f2mul(t1, v[q]);    // (S2[q], S2[q+8])
            float s1l, s1h, s2l, s2h;
            upk(t1, s1l, s1h);
            upk(t2, s2l, s2h);
            float ml = (lane & 16) ? s2l : s1l;
            float gl = (lane & 16) ? s1l : s2l;
            a16[2 * q] = ml + __shfl_xor_sync(0xffffffffu, gl, 16);
            float mh = (lane & 16) ? s2h : s1h;
            float gh = (lane & 16) ? s1h : s2h;
            a16[2 * q + 1] = mh + __shfl_xor_sync(0xffffffffu, gh, 16);
        }
        // lane L: S1[perm(L)] (L<16) / S2[perm(L-16)], perm(m) = (m>>1) + (m&1)*8
        red_s[wid][o][lane] = bfly16_tail(a16, lane);
    }
    // S0 for all o in one distributed reduce
    {
        float val[16];
#pragma unroll
        for (int i = 0; i < 16; i++) val[i] = (i < OO) ? rp[i] : 0.f;
        float s0 = bfly16_full(val, lane);
        int o = lane >> 1;
        if (!(lane & 1) && o < OO) red0_s[wid][o] = s0;
    }
    __syncthreads();

    // Single block-level fold: 330 outputs
    for (int it = tid; it < OO * 33; it += 256) {
        int o = it / 33, t = it % 33;
        float s = 0.f;
#pragma unroll
        for (int wdx = 0; wdx < NW; wdx++)
            s += (t < 32) ? red_s[wdx][o][t] : red0_s[wdx][o];
        g_partials[((b * OO + o) * NBLK + nb) * 36 + t] = s;
    }
}

__global__ void __launch_bounds__(64) finalize_kernel(const float* __restrict__ beta_a,
                                                      const float* __restrict__ beta_v,
                                                      float inv_temp, int is_final,
                                                      float* __restrict__ out) {
    __shared__ float sums[36];
    const int o = blockIdx.x, b = blockIdx.y, t = threadIdx.x;
    if (t < 33) {
        const size_t base = (size_t)(b * OO + o) * NBLK * 36;
        float s = 0.f;
#pragma unroll
        for (int k = 0; k < NBLK; k++) s += g_partials[base + k * 36 + t];
        sums[t] = s;
    }
    __syncthreads();
    if (t < 16) {
        // inverse perm: value for h=t lives at index ip
        const int ip = (t < 8) ? 2 * t : 2 * (t - 8) + 1;
        float S0 = sums[32];
        float S1 = sums[ip], S2 = sums[16 + ip];
        float inv = 1.f / (S0 + EPSV);
        float mean = S1 * inv;
        float raw = S2 - mean * (2.f * S1 - mean * S0);  // == sum rp*(v-mean)^2 exactly
        float var = fmaxf(raw * inv, 0.f) + EPSV;
        float hv = 0.5f / var;
        float lv = logf(var);
        float hvm2 = hv * mean * mean;
        float lvs = lv, ms = hvm2;
#pragma unroll
        for (int off = 8; off; off >>= 1) {
            lvs += __shfl_down_sync(0x0000ffffu, lvs, off);
            ms += __shfl_down_sync(0x0000ffffu, ms, off);
        }
        const int pbase = (b * OO + o) * 40;
        if (is_final) {
            out[((size_t)b * OO + o) * 16 + t] = mean;
        } else {
            g_params[pbase + ip] = -2.f * hv * mean;   // c1
            g_params[pbase + 16 + ip] = hv;            // hv
        }
        if (t == 0) {
            float bv = beta_v[o], ba = beta_a[o];
            float cost = S0 * fmaf(0.5f, lvs, 16.f * bv);
            float actj = 1.f / (1.f + expf(-inv_temp * (ba - cost)));
            if (is_final) {
                out[(size_t)BB * OO * 16 + b * OO + o] = actj;
            } else {
                // c0 = log(act+eps) - 0.5*(16*log(2pi) + sum lv) - sum hv*m^2
                g_params[pbase + 32] =
                    logf(actj + EPSV) - 0.5f * (16.f * 1.8378770664093453f + lvs) - ms;
            }
        }
    }
}

extern "C" void kernel_launch(void* const* d_in, const int* in_sizes, int n_in,
                              void* d_out, int out_size) {
    const float* pose = (const float*)d_in[0];
    const float* act  = (const float*)d_in[1];
    const float* w    = (const float*)d_in[2];
    const float* ba   = (const float*)d_in[3];
    const float* bv   = (const float*)d_in[4];
    float* out = (float*)d_out;

    dim3 gp(NBLK, BB);
    dim3 gf(OO, BB);
    em_pass_kernel<true><<<gp, 256>>>(pose, act, w);
    finalize_kernel<<<gf, 64>>>(ba, bv, 0.0005f, 0, out);
    em_pass_kernel<false><<<gp, 256>>>(pose, act, w);
    finalize_kernel<<<gf, 64>>>(ba, bv, 0.000975f, 0, out);
    em_pass_kernel<false><<<gp, 256>>>(pose, act, w);
    finalize_kernel<<<gf, 64>>>(ba, bv, 0.00142625f, 1, out);
}

// round 8
// speedup vs baseline: 1.1529x; 1.1529x over previous
#include <cuda_runtime.h>
#include <cstdint>

// R8 = verbatim resubmit of R7 (container infra flake, same as R0/R5; R6 precedent:
// identical resubmit succeeded). See theory for the re-audit of the factorized it-0 path.

#define BB 64
#define SS 14
#define NSP (SS*SS)      // 196
#define CC 32
#define NN (NSP*CC)      // 6272
#define OO 10
#define HH 16
#define EPSV 1e-9f
#define NBLK 25          // 25*256 = 6400 >= 6272
#define NW 8             // warps per block
#define NCH 8            // spatial chunks for first_stats

typedef unsigned long long u64;

// Scratch
__device__ float g_partials[BB * OO * NBLK * 36]; // 0..15 S1[perm], 16..31 S2[perm], 32 S0
__device__ float g_params[BB * OO * 40];          // 0..15 c1[ip], 16..31 hv[ip], 32 c0
__device__ float g_fstats[BB * NCH * 72 * 32];    // [b][ch][idx][c], idx<69 used

// ---- f32x2 packed helpers ----
__device__ __forceinline__ u64 pk(float lo, float hi) {
    u64 r; asm("mov.b64 %0, {%1,%2};" : "=l"(r) : "f"(lo), "f"(hi)); return r;
}
__device__ __forceinline__ u64 pkd(float x) {
    u64 r; asm("mov.b64 %0, {%1,%1};" : "=l"(r) : "f"(x)); return r;
}
__device__ __forceinline__ void upk(u64 a, float& lo, float& hi) {
    asm("mov.b64 {%0,%1}, %2;" : "=f"(lo), "=f"(hi) : "l"(a));
}
__device__ __forceinline__ u64 f2fma(u64 a, u64 b, u64 c) {
    u64 d; asm("fma.rn.f32x2 %0, %1, %2, %3;" : "=l"(d) : "l"(a), "l"(b), "l"(c)); return d;
}
__device__ __forceinline__ u64 f2mul(u64 a, u64 b) {
    u64 d; asm("mul.rn.f32x2 %0, %1, %2;" : "=l"(d) : "l"(a), "l"(b)); return d;
}
__device__ __forceinline__ u64 f2add(u64 a, u64 b) {
    u64 d; asm("add.rn.f32x2 %0, %1, %2;" : "=l"(d) : "l"(a), "l"(b)); return d;
}

__device__ __forceinline__ float warp_red(float v) {
    v += __shfl_down_sync(0xffffffffu, v, 16);
    v += __shfl_down_sync(0xffffffffu, v, 8);
    v += __shfl_down_sync(0xffffffffu, v, 4);
    v += __shfl_down_sync(0xffffffffu, v, 2);
    v += __shfl_down_sync(0xffffffffu, v, 1);
    return v;
}

// Butterfly stages 8..1 on a 16-value distributed set.
__device__ __forceinline__ float bfly16_tail(float a16[16], int lane) {
    float a8[8];
#pragma unroll
    for (int i = 0; i < 8; i++) {
        float mine = (lane & 8) ? a16[i + 8] : a16[i];
        float give = (lane & 8) ? a16[i] : a16[i + 8];
        a8[i] = mine + __shfl_xor_sync(0xffffffffu, give, 8);
    }
    float a4[4];
#pragma unroll
    for (int i = 0; i < 4; i++) {
        float mine = (lane & 4) ? a8[i + 4] : a8[i];
        float give = (lane & 4) ? a8[i] : a8[i + 4];
        a4[i] = mine + __shfl_xor_sync(0xffffffffu, give, 4);
    }
    float a2[2];
#pragma unroll
    for (int i = 0; i < 2; i++) {
        float mine = (lane & 2) ? a4[i + 2] : a4[i];
        float give = (lane & 2) ? a4[i] : a4[i + 2];
        a2[i] = mine + __shfl_xor_sync(0xffffffffu, give, 2);
    }
    float mine = (lane & 1) ? a2[1] : a2[0];
    float give = (lane & 1) ? a2[0] : a2[1];
    return mine + __shfl_xor_sync(0xffffffffu, give, 1);
}

// Clean distributed reduce of 32 values: lane L ends with total of val[L].
__device__ __forceinline__ float bfly32_full(const float val[32], int lane) {
    float a16[16];
#pragma unroll
    for (int i = 0; i < 16; i++) {
        float mine = (lane & 16) ? val[i + 16] : val[i];
        float give = (lane & 16) ? val[i] : val[i + 16];
        a16[i] = mine + __shfl_xor_sync(0xffffffffu, give, 16);
    }
    return bfly16_tail(a16, lane);
}

// Distributed reduce of 16 values: lane L gets total of value (L>>1)&15.
__device__ __forceinline__ float bfly16_full(const float val[16], int lane) {
    float v8[8];
#pragma unroll
    for (int i = 0; i < 8; i++) {
        float mine = (lane & 16) ? val[i + 8] : val[i];
        float give = (lane & 16) ? val[i] : val[i + 8];
        v8[i] = mine + __shfl_xor_sync(0xffffffffu, give, 16);
    }
    float v4[4];
#pragma unroll
    for (int i = 0; i < 4; i++) {
        float mine = (lane & 8) ? v8[i + 4] : v8[i];
        float give = (lane & 8) ? v8[i] : v8[i + 4];
        v4[i] = mine + __shfl_xor_sync(0xffffffffu, give, 8);
    }
    float v2[2];
#pragma unroll
    for (int i = 0; i < 2; i++) {
        float mine = (lane & 4) ? v4[i + 2] : v4[i];
        float give = (lane & 4) ? v4[i] : v4[i + 2];
        v2[i] = mine + __shfl_xor_sync(0xffffffffu, give, 4);
    }
    float mine = (lane & 2) ? v2[1] : v2[0];
    float give = (lane & 2) ? v2[0] : v2[1];
    float v1 = mine + __shfl_xor_sync(0xffffffffu, give, 2);
    return v1 + __shfl_xor_sync(0xffffffffu, v1, 1);
}

// ===================== FIRST-iteration factorized stats =====================
// Per (b, chunk, c): A1[16]=Σa·p, G[4][10]=Σa·(p_i⊗p_i) sym, Xr/Xc[4]=Σa·coord·p0j,
// scalars Σa, Σa·cr, Σa·cr², Σa·cc, Σa·cc².
__global__ void __launch_bounds__(64) first_stats_kernel(const float* __restrict__ pose,
                                                         const float* __restrict__ act) {
    const int g = blockIdx.x * 2 + (threadIdx.x >> 5);  // 0..511
    const int c = threadIdx.x & 31;
    const int b = g >> 3, ch = g & 7;

    float A1[16], G[40], Xr[4], Xc[4], sc[5];
#pragma unroll
    for (int i = 0; i < 16; i++) A1[i] = 0.f;
#pragma unroll
    for (int i = 0; i < 40; i++) G[i] = 0.f;
#pragma unroll
    for (int i = 0; i < 4; i++) { Xr[i] = 0.f; Xc[i] = 0.f; }
#pragma unroll
    for (int i = 0; i < 5; i++) sc[i] = 0.f;

    for (int sp = ch; sp < NSP; sp += NCH) {
        const float4* pp = reinterpret_cast<const float4*>(pose) +
                           (size_t)((b * NSP + sp) * CC + c) * 4;
        float4 q0 = pp[0], q1 = pp[1], q2 = pp[2], q3 = pp[3];
        float p[16] = {q0.x, q0.y, q0.z, q0.w, q1.x, q1.y, q1.z, q1.w,
                       q2.x, q2.y, q2.z, q2.w, q3.x, q3.y, q3.z, q3.w};
        float a = act[(size_t)b * NN + sp * CC + c];
        float cr = (sp / SS + 0.5f) * (1.f / SS);
        float cw = (sp % SS + 0.5f) * (1.f / SS);
        float ap[16];
#pragma unroll
        for (int i = 0; i < 16; i++) { ap[i] = a * p[i]; A1[i] += ap[i]; }
#pragma unroll
        for (int i = 0; i < 4; i++) {
            const float* pi = p + i * 4;
            const float* ai = ap + i * 4;
            float* Gi = G + i * 10;
            Gi[0] += ai[0] * pi[0]; Gi[1] += ai[0] * pi[1];
            Gi[2] += ai[0] * pi[2]; Gi[3] += ai[0] * pi[3];
            Gi[4] += ai[1] * pi[1]; Gi[5] += ai[1] * pi[2];
            Gi[6] += ai[1] * pi[3]; Gi[7] += ai[2] * pi[2];
            Gi[8] += ai[2] * pi[3]; Gi[9] += ai[3] * pi[3];
        }
        float acr = a * cr, acc = a * cw;
#pragma unroll
        for (int j = 0; j < 4; j++) { Xr[j] += acr * p[j]; Xc[j] += acc * p[j]; }
        sc[0] += a; sc[1] += acr; sc[2] += acr * cr; sc[3] += acc; sc[4] += acc * cw;
    }

    float* st = g_fstats + (size_t)((b * NCH + ch) * 72) * 32 + c;
#pragma unroll
    for (int i = 0; i < 16; i++) st[i * 32] = A1[i];
#pragma unroll
    for (int i = 0; i < 40; i++) st[(16 + i) * 32] = G[i];
#pragma unroll
    for (int j = 0; j < 4; j++) { st[(56 + j) * 32] = Xr[j]; st[(60 + j) * 32] = Xc[j]; }
#pragma unroll
    for (int k = 0; k < 5; k++) st[(64 + k) * 32] = sc[k];
}

// Contract stats with W into S1/S2/S0, write g_partials slot 0 (perm layout).
__global__ void __launch_bounds__(320) first_contract_kernel(const float* __restrict__ w) {
    __shared__ float st_s[69 * 32];
    const int b = blockIdx.x, tid = threadIdx.x;
    // fold chunks while loading
    for (int e = tid; e < 69 * 32; e += 320) {
        float s = 0.f;
#pragma unroll
        for (int ch = 0; ch < NCH; ch++)
            s += g_fstats[(size_t)((b * NCH + ch) * 72) * 32 + e];
        st_s[e] = s;
    }
    __syncthreads();

    const int wid = tid >> 5, lane = tid & 31;
    if (wid >= OO) return;
    const int o = wid, c = lane;

    // load weights w[c][o][j][k]
    const float4* wg4 = reinterpret_cast<const float4*>(w) + (c * OO + o) * 4;
    float4 r0 = wg4[0], r1 = wg4[1], r2 = wg4[2], r3 = wg4[3];
    float wjk[4][4] = {{r0.x, r0.y, r0.z, r0.w}, {r1.x, r1.y, r1.z, r1.w},
                       {r2.x, r2.y, r2.z, r2.w}, {r3.x, r3.y, r3.z, r3.w}};

    float A1[16], G[40], Xr[4], Xc[4];
#pragma unroll
    for (int i = 0; i < 16; i++) A1[i] = st_s[i * 32 + c];
#pragma unroll
    for (int i = 0; i < 40; i++) G[i] = st_s[(16 + i) * 32 + c];
#pragma unroll
    for (int j = 0; j < 4; j++) { Xr[j] = st_s[(56 + j) * 32 + c]; Xc[j] = st_s[(60 + j) * 32 + c]; }
    float s_a = st_s[64 * 32 + c], s_acr = st_s[65 * 32 + c], s_acr2 = st_s[66 * 32 + c];
    float s_acc = st_s[67 * 32 + c], s_acc2 = st_s[68 * 32 + c];

    float m1[16], s2[16];
#pragma unroll
    for (int k = 0; k < 4; k++) {
        float w0 = wjk[0][k], w1 = wjk[1][k], w2 = wjk[2][k], w3 = wjk[3][k];
        float wp[10];
        wp[0] = w0 * w0;        wp[1] = 2.f * w0 * w1; wp[2] = 2.f * w0 * w2;
        wp[3] = 2.f * w0 * w3;  wp[4] = w1 * w1;       wp[5] = 2.f * w1 * w2;
        wp[6] = 2.f * w1 * w3;  wp[7] = w2 * w2;       wp[8] = 2.f * w2 * w3;
        wp[9] = w3 * w3;
#pragma unroll
        for (int i = 0; i < 4; i++) {
            const float* Ai = A1 + i * 4;
            const float* Gi = G + i * 10;
            m1[i * 4 + k] = Ai[0] * w0 + Ai[1] * w1 + Ai[2] * w2 + Ai[3] * w3;
            float s = Gi[0] * wp[0] + Gi[1] * wp[1] + Gi[2] * wp[2] + Gi[3] * wp[3] +
                      Gi[4] * wp[4] + Gi[5] * wp[5] + Gi[6] * wp[6] + Gi[7] * wp[7] +
                      Gi[8] * wp[8] + Gi[9] * wp[9];
            s2[i * 4 + k] = s;
        }
    }
    // coord terms: h=0 gets +cr, h=1 gets +cc
    m1[0] += s_acr;
    s2[0] += s_acr2 + 2.f * (Xr[0] * wjk[0][0] + Xr[1] * wjk[1][0] +
                             Xr[2] * wjk[2][0] + Xr[3] * wjk[3][0]);
    m1[1] += s_acc;
    s2[1] += s_acc2 + 2.f * (Xc[0] * wjk[0][1] + Xc[1] * wjk[1][1] +
                             Xc[2] * wjk[2][1] + Xc[3] * wjk[3][1]);

    // perm layout to match em_pass/finalize: val[L] = S1[perm(L)] / S2[perm(L-16)]
    float val[32];
#pragma unroll
    for (int L = 0; L < 16; L++) {
        int h = (L >> 1) + (L & 1) * 8;
        val[L] = m1[h];
        val[16 + L] = s2[h];
    }
    float r = bfly32_full(val, lane) * 0.1f;  // rr = 1/10
    float s0 = warp_red(s_a);
    float* gp = &g_partials[(size_t)((b * OO + o) * NBLK + 0) * 36];
    gp[lane] = r;
    if (lane == 0) gp[32] = s0 * 0.1f;
}

// ===================== EM iterations 1,2 (full routing) =====================
__global__ void __launch_bounds__(256, 3) em_pass_kernel(const float* __restrict__ pose,
                                                         const float* __restrict__ act,
                                                         const float* __restrict__ w) {
    __shared__ __align__(16) float4 w_s4[OO * 4 * 32];  // [r=o*4+j][c], 20KB
    __shared__ __align__(16) float p_s[OO * 36];        // c1[16], hv[16], c0
    __shared__ float red_s[NW][OO][32];
    __shared__ float red0_s[NW][16];

    const int b = blockIdx.y, nb = blockIdx.x;
    const int tid = threadIdx.x, lane = tid & 31, wid = tid >> 5;

    const float4* wg4 = reinterpret_cast<const float4*>(w);
    for (int idx = tid; idx < CC * 40; idx += 256) {
        int ci = idx / 40, r = idx % 40;
        w_s4[r * 32 + ci] = wg4[idx];
    }
    for (int idx = tid; idx < OO * 36; idx += 256) {
        int o = idx / 36, t = idx % 36;
        p_s[idx] = (t < 33) ? g_params[(b * OO + o) * 40 + t] : 0.f;
    }
    __syncthreads();

    const int n = nb * 256 + tid;
    const bool valid = n < NN;
    const int nn = valid ? n : (NN - 1);
    const int ns = nn >> 5, c = nn & 31;
    const float4* pp = reinterpret_cast<const float4*>(pose) +
                       (size_t)((b * NSP + ns) * CC + c) * 4;
    float4 R0 = pp[0], R1 = pp[1], R2 = pp[2], R3 = pp[3];
    const float a = valid ? act[(size_t)b * NN + n] : 0.f;
    const int s1 = ns / SS, s2i = ns % SS;
    const u64 cp0 = pk((s1 + 0.5f) * (1.f / SS), 0.f);
    const u64 cp1 = pk((s2i + 0.5f) * (1.f / SS), 0.f);

    u64 P2[8];
    P2[0] = pk(R0.x, R2.x); P2[1] = pk(R0.y, R2.y); P2[2] = pk(R0.z, R2.z); P2[3] = pk(R0.w, R2.w);
    P2[4] = pk(R1.x, R3.x); P2[5] = pk(R1.y, R3.y); P2[6] = pk(R1.z, R3.z); P2[7] = pk(R1.w, R3.w);

    auto votes = [&](int o, u64 v[8]) {
        const float4* wp = w_s4 + (o * 4) * 32 + c;
        {
            float4 W = wp[0];
            u64 w0 = pkd(W.x), w1 = pkd(W.y), w2 = pkd(W.z), w3 = pkd(W.w);
            v[0] = f2mul(P2[0], w0); v[1] = f2mul(P2[0], w1);
            v[2] = f2mul(P2[0], w2); v[3] = f2mul(P2[0], w3);
            v[4] = f2mul(P2[4], w0); v[5] = f2mul(P2[4], w1);
            v[6] = f2mul(P2[4], w2); v[7] = f2mul(P2[4], w3);
        }
#pragma unroll
        for (int j = 1; j < 4; j++) {
            float4 W = wp[j * 32];
            u64 w0 = pkd(W.x), w1 = pkd(W.y), w2 = pkd(W.z), w3 = pkd(W.w);
            v[0] = f2fma(P2[j], w0, v[0]); v[1] = f2fma(P2[j], w1, v[1]);
            v[2] = f2fma(P2[j], w2, v[2]); v[3] = f2fma(P2[j], w3, v[3]);
            v[4] = f2fma(P2[4 + j], w0, v[4]); v[5] = f2fma(P2[4 + j], w1, v[5]);
            v[6] = f2fma(P2[4 + j], w2, v[6]); v[7] = f2fma(P2[4 + j], w3, v[7]);
        }
        v[0] = f2add(v[0], cp0);
        v[1] = f2add(v[1], cp1);
    };

    float rp[OO];
    // Pass A: la[o] = c0 - sum_h v*(hv*v + c1)
#pragma unroll 2
    for (int o = 0; o < OO; o++) {
        u64 v[8];
        votes(o, v);
        const u64* mp = reinterpret_cast<const u64*>(p_s + o * 36);
        u64 apx = 0;
#pragma unroll
        for (int q = 0; q < 8; q++) {
            u64 t = f2fma(mp[8 + q], v[q], mp[q]);
            apx = f2fma(t, v[q], apx);
        }
        float l, h;
        upk(apx, l, h);
        rp[o] = p_s[o * 36 + 32] - (l + h);
    }
    {
        float mx = rp[0];
#pragma unroll
        for (int o = 1; o < OO; o++) mx = fmaxf(mx, rp[o]);
        float s = 0.f;
#pragma unroll
        for (int o = 0; o < OO; o++) { rp[o] = __expf(rp[o] - mx); s += rp[o]; }
        float scl = a / s;
#pragma unroll
        for (int o = 0; o < OO; o++) rp[o] *= scl;
    }

    // Pass B
#pragma unroll 2
    for (int o = 0; o < OO; o++) {
        u64 v[8];
        votes(o, v);
        u64 rpp = pkd(rp[o]);
        float a16[16];
#pragma unroll
        for (int q = 0; q < 8; q++) {
            u64 t1 = f2mul(rpp, v[q]);
            u64 t2 = f2mul(t1, v[q]);
            float s1l, s1h, s2l, s2h;
            upk(t1, s1l, s1h);
            upk(t2, s2l, s2h);
            float ml = (lane & 16) ? s2l : s1l;
            float gl = (lane & 16) ? s1l : s2l;
            a16[2 * q] = ml + __shfl_xor_sync(0xffffffffu, gl, 16);
            float mh = (lane & 16) ? s2h : s1h;
            float gh = (lane & 16) ? s1h : s2h;
            a16[2 * q + 1] = mh + __shfl_xor_sync(0xffffffffu, gh, 16);
        }
        red_s[wid][o][lane] = bfly16_tail(a16, lane);
    }
    {
        float val[16];
#pragma unroll
        for (int i = 0; i < 16; i++) val[i] = (i < OO) ? rp[i] : 0.f;
        float s0 = bfly16_full(val, lane);
        int o = lane >> 1;
        if (!(lane & 1) && o < OO) red0_s[wid][o] = s0;
    }
    __syncthreads();

    for (int it = tid; it < OO * 33; it += 256) {
        int o = it / 33, t = it % 33;
        float s = 0.f;
#pragma unroll
        for (int wdx = 0; wdx < NW; wdx++)
            s += (t < 32) ? red_s[wdx][o][t] : red0_s[wdx][o];
        g_partials[((b * OO + o) * NBLK + nb) * 36 + t] = s;
    }
}

__global__ void __launch_bounds__(64) finalize_kernel(const float* __restrict__ beta_a,
                                                      const float* __restrict__ beta_v,
                                                      float inv_temp, int is_final, int nblk,
                                                      float* __restrict__ out) {
    __shared__ float sums[36];
    const int o = blockIdx.x, b = blockIdx.y, t = threadIdx.x;
    if (t < 33) {
        const size_t base = (size_t)(b * OO + o) * NBLK * 36;
        float s = 0.f;
        for (int k = 0; k < nblk; k++) s += g_partials[base + k * 36 + t];
        sums[t] = s;
    }
    __syncthreads();
    if (t < 16) {
        const int ip = (t < 8) ? 2 * t : 2 * (t - 8) + 1;
        float S0 = sums[32];
        float S1 = sums[ip], S2 = sums[16 + ip];
        float inv = 1.f / (S0 + EPSV);
        float mean = S1 * inv;
        float raw = S2 - mean * (2.f * S1 - mean * S0);
        float var = fmaxf(raw * inv, 0.f) + EPSV;
        float hv = 0.5f / var;
        float lv = logf(var);
        float hvm2 = hv * mean * mean;
        float lvs = lv, ms = hvm2;
#pragma unroll
        for (int off = 8; off; off >>= 1) {
            lvs += __shfl_down_sync(0x0000ffffu, lvs, off);
            ms += __shfl_down_sync(0x0000ffffu, ms, off);
        }
        const int pbase = (b * OO + o) * 40;
        if (is_final) {
            out[((size_t)b * OO + o) * 16 + t] = mean;
        } else {
            g_params[pbase + ip] = -2.f * hv * mean;   // c1
            g_params[pbase + 16 + ip] = hv;            // hv
        }
        if (t == 0) {
            float bv = beta_v[o], ba = beta_a[o];
            float cost = S0 * fmaf(0.5f, lvs, 16.f * bv);
            float actj = 1.f / (1.f + expf(-inv_temp * (ba - cost)));
            if (is_final) {
                out[(size_t)BB * OO * 16 + b * OO + o] = actj;
            } else {
                g_params[pbase + 32] =
                    logf(actj + EPSV) - 0.5f * (16.f * 1.8378770664093453f + lvs) - ms;
            }
        }
    }
}

extern "C" void kernel_launch(void* const* d_in, const int* in_sizes, int n_in,
                              void* d_out, int out_size) {
    const float* pose = (const float*)d_in[0];
    const float* act  = (const float*)d_in[1];
    const float* w    = (const float*)d_in[2];
    const float* ba   = (const float*)d_in[3];
    const float* bv   = (const float*)d_in[4];
    float* out = (float*)d_out;

    dim3 gp(NBLK, BB);
    dim3 gf(OO, BB);
    // it 0 (factorized): stats + contract + finalize(nblk=1)
    first_stats_kernel<<<256, 64>>>(pose, act);
    first_contract_kernel<<<BB, 320>>>(w);
    finalize_kernel<<<gf, 64>>>(ba, bv, 0.0005f, 0, 1, out);
    // it 1
    em_pass_kernel<<<gp, 256>>>(pose, act, w);
    finalize_kernel<<<gf, 64>>>(ba, bv, 0.000975f, 0, NBLK, out);
    // it 2 (final)  — launch index 5 = em_pass (ncu -s 5 captures it)
    em_pass_kernel<<<gp, 256>>>(pose, act, w);
    finalize_kernel<<<gf, 64>>>(ba, bv, 0.00142625f, 1, NBLK, out);
}

// round 9
// speedup vs baseline: 1.3427x; 1.1646x over previous
#include <cuda_runtime.h>
#include <cstdint>

#define BB 64
#define SS 14
#define NSP (SS*SS)      // 196
#define CC 32
#define NN (NSP*CC)      // 6272
#define OO 10
#define HH 16
#define EPSV 1e-9f
#define NBLK 13          // 13*512 = 6656 >= 6272 (2 items/thread, 256 threads)
#define NW 8             // warps per block
#define NCH 8            // spatial chunks for first_stats

typedef unsigned long long u64;

// Scratch
__device__ float g_partials[BB * OO * NBLK * 36]; // 0..15 S1[perm], 16..31 S2[perm], 32 S0
__device__ float g_params[BB * OO * 40];          // 0..15 c1[ip], 16..31 hv[ip], 32 c0
__device__ float g_fstats[BB * NCH * 72 * 32];    // [b][ch][idx][c], idx<69 used

// ---- f32x2 packed helpers ----
__device__ __forceinline__ u64 pk(float lo, float hi) {
    u64 r; asm("mov.b64 %0, {%1,%2};" : "=l"(r) : "f"(lo), "f"(hi)); return r;
}
__device__ __forceinline__ u64 pkd(float x) {
    u64 r; asm("mov.b64 %0, {%1,%1};" : "=l"(r) : "f"(x)); return r;
}
__device__ __forceinline__ void upk(u64 a, float& lo, float& hi) {
    asm("mov.b64 {%0,%1}, %2;" : "=f"(lo), "=f"(hi) : "l"(a));
}
__device__ __forceinline__ u64 f2fma(u64 a, u64 b, u64 c) {
    u64 d; asm("fma.rn.f32x2 %0, %1, %2, %3;" : "=l"(d) : "l"(a), "l"(b), "l"(c)); return d;
}
__device__ __forceinline__ u64 f2mul(u64 a, u64 b) {
    u64 d; asm("mul.rn.f32x2 %0, %1, %2;" : "=l"(d) : "l"(a), "l"(b)); return d;
}
__device__ __forceinline__ u64 f2add(u64 a, u64 b) {
    u64 d; asm("add.rn.f32x2 %0, %1, %2;" : "=l"(d) : "l"(a), "l"(b)); return d;
}

__device__ __forceinline__ float warp_red(float v) {
    v += __shfl_down_sync(0xffffffffu, v, 16);
    v += __shfl_down_sync(0xffffffffu, v, 8);
    v += __shfl_down_sync(0xffffffffu, v, 4);
    v += __shfl_down_sync(0xffffffffu, v, 2);
    v += __shfl_down_sync(0xffffffffu, v, 1);
    return v;
}

// Butterfly stages 8..1 on a 16-value distributed set.
__device__ __forceinline__ float bfly16_tail(float a16[16], int lane) {
    float a8[8];
#pragma unroll
    for (int i = 0; i < 8; i++) {
        float mine = (lane & 8) ? a16[i + 8] : a16[i];
        float give = (lane & 8) ? a16[i] : a16[i + 8];
        a8[i] = mine + __shfl_xor_sync(0xffffffffu, give, 8);
    }
    float a4[4];
#pragma unroll
    for (int i = 0; i < 4; i++) {
        float mine = (lane & 4) ? a8[i + 4] : a8[i];
        float give = (lane & 4) ? a8[i] : a8[i + 4];
        a4[i] = mine + __shfl_xor_sync(0xffffffffu, give, 4);
    }
    float a2[2];
#pragma unroll
    for (int i = 0; i < 2; i++) {
        float mine = (lane & 2) ? a4[i + 2] : a4[i];
        float give = (lane & 2) ? a4[i] : a4[i + 2];
        a2[i] = mine + __shfl_xor_sync(0xffffffffu, give, 2);
    }
    float mine = (lane & 1) ? a2[1] : a2[0];
    float give = (lane & 1) ? a2[0] : a2[1];
    return mine + __shfl_xor_sync(0xffffffffu, give, 1);
}

// Clean distributed reduce of 32 values: lane L ends with total of val[L].
__device__ __forceinline__ float bfly32_full(const float val[32], int lane) {
    float a16[16];
#pragma unroll
    for (int i = 0; i < 16; i++) {
        float mine = (lane & 16) ? val[i + 16] : val[i];
        float give = (lane & 16) ? val[i] : val[i + 16];
        a16[i] = mine + __shfl_xor_sync(0xffffffffu, give, 16);
    }
    return bfly16_tail(a16, lane);
}

// Distributed reduce of 16 values: lane L gets total of value (L>>1)&15.
__device__ __forceinline__ float bfly16_full(const float val[16], int lane) {
    float v8[8];
#pragma unroll
    for (int i = 0; i < 8; i++) {
        float mine = (lane & 16) ? val[i + 8] : val[i];
        float give = (lane & 16) ? val[i] : val[i + 8];
        v8[i] = mine + __shfl_xor_sync(0xffffffffu, give, 16);
    }
    float v4[4];
#pragma unroll
    for (int i = 0; i < 4; i++) {
        float mine = (lane & 8) ? v8[i + 4] : v8[i];
        float give = (lane & 8) ? v8[i] : v8[i + 4];
        v4[i] = mine + __shfl_xor_sync(0xffffffffu, give, 8);
    }
    float v2[2];
#pragma unroll
    for (int i = 0; i < 2; i++) {
        float mine = (lane & 4) ? v4[i + 2] : v4[i];
        float give = (lane & 4) ? v4[i] : v4[i + 2];
        v2[i] = mine + __shfl_xor_sync(0xffffffffu, give, 4);
    }
    float mine = (lane & 2) ? v2[1] : v2[0];
    float give = (lane & 2) ? v2[0] : v2[1];
    float v1 = mine + __shfl_xor_sync(0xffffffffu, give, 2);
    return v1 + __shfl_xor_sync(0xffffffffu, v1, 1);
}

// ===================== FIRST-iteration factorized stats =====================
__global__ void __launch_bounds__(64) first_stats_kernel(const float* __restrict__ pose,
                                                         const float* __restrict__ act) {
    const int g = blockIdx.x * 2 + (threadIdx.x >> 5);  // 0..511
    const int c = threadIdx.x & 31;
    const int b = g >> 3, ch = g & 7;

    float A1[16], G[40], Xr[4], Xc[4], sc[5];
#pragma unroll
    for (int i = 0; i < 16; i++) A1[i] = 0.f;
#pragma unroll
    for (int i = 0; i < 40; i++) G[i] = 0.f;
#pragma unroll
    for (int i = 0; i < 4; i++) { Xr[i] = 0.f; Xc[i] = 0.f; }
#pragma unroll
    for (int i = 0; i < 5; i++) sc[i] = 0.f;

    for (int sp = ch; sp < NSP; sp += NCH) {
        const float4* pp = reinterpret_cast<const float4*>(pose) +
                           (size_t)((b * NSP + sp) * CC + c) * 4;
        float4 q0 = pp[0], q1 = pp[1], q2 = pp[2], q3 = pp[3];
        float p[16] = {q0.x, q0.y, q0.z, q0.w, q1.x, q1.y, q1.z, q1.w,
                       q2.x, q2.y, q2.z, q2.w, q3.x, q3.y, q3.z, q3.w};
        float a = act[(size_t)b * NN + sp * CC + c];
        float cr = (sp / SS + 0.5f) * (1.f / SS);
        float cw = (sp % SS + 0.5f) * (1.f / SS);
        float ap[16];
#pragma unroll
        for (int i = 0; i < 16; i++) { ap[i] = a * p[i]; A1[i] += ap[i]; }
#pragma unroll
        for (int i = 0; i < 4; i++) {
            const float* pi = p + i * 4;
            const float* ai = ap + i * 4;
            float* Gi = G + i * 10;
            Gi[0] += ai[0] * pi[0]; Gi[1] += ai[0] * pi[1];
            Gi[2] += ai[0] * pi[2]; Gi[3] += ai[0] * pi[3];
            Gi[4] += ai[1] * pi[1]; Gi[5] += ai[1] * pi[2];
            Gi[6] += ai[1] * pi[3]; Gi[7] += ai[2] * pi[2];
            Gi[8] += ai[2] * pi[3]; Gi[9] += ai[3] * pi[3];
        }
        float acr = a * cr, acc = a * cw;
#pragma unroll
        for (int j = 0; j < 4; j++) { Xr[j] += acr * p[j]; Xc[j] += acc * p[j]; }
        sc[0] += a; sc[1] += acr; sc[2] += acr * cr; sc[3] += acc; sc[4] += acc * cw;
    }

    float* st = g_fstats + (size_t)((b * NCH + ch) * 72) * 32 + c;
#pragma unroll
    for (int i = 0; i < 16; i++) st[i * 32] = A1[i];
#pragma unroll
    for (int i = 0; i < 40; i++) st[(16 + i) * 32] = G[i];
#pragma unroll
    for (int j = 0; j < 4; j++) { st[(56 + j) * 32] = Xr[j]; st[(60 + j) * 32] = Xc[j]; }
#pragma unroll
    for (int k = 0; k < 5; k++) st[(64 + k) * 32] = sc[k];
}

__global__ void __launch_bounds__(320) first_contract_kernel(const float* __restrict__ w) {
    __shared__ float st_s[69 * 32];
    const int b = blockIdx.x, tid = threadIdx.x;
    for (int e = tid; e < 69 * 32; e += 320) {
        float s = 0.f;
#pragma unroll
        for (int ch = 0; ch < NCH; ch++)
            s += g_fstats[(size_t)((b * NCH + ch) * 72) * 32 + e];
        st_s[e] = s;
    }
    __syncthreads();

    const int wid = tid >> 5, lane = tid & 31;
    if (wid >= OO) return;
    const int o = wid, c = lane;

    const float4* wg4 = reinterpret_cast<const float4*>(w) + (c * OO + o) * 4;
    float4 r0 = wg4[0], r1 = wg4[1], r2 = wg4[2], r3 = wg4[3];
    float wjk[4][4] = {{r0.x, r0.y, r0.z, r0.w}, {r1.x, r1.y, r1.z, r1.w},
                       {r2.x, r2.y, r2.z, r2.w}, {r3.x, r3.y, r3.z, r3.w}};

    float A1[16], G[40], Xr[4], Xc[4];
#pragma unroll
    for (int i = 0; i < 16; i++) A1[i] = st_s[i * 32 + c];
#pragma unroll
    for (int i = 0; i < 40; i++) G[i] = st_s[(16 + i) * 32 + c];
#pragma unroll
    for (int j = 0; j < 4; j++) { Xr[j] = st_s[(56 + j) * 32 + c]; Xc[j] = st_s[(60 + j) * 32 + c]; }
    float s_a = st_s[64 * 32 + c], s_acr = st_s[65 * 32 + c], s_acr2 = st_s[66 * 32 + c];
    float s_acc = st_s[67 * 32 + c], s_acc2 = st_s[68 * 32 + c];

    float m1[16], s2[16];
#pragma unroll
    for (int k = 0; k < 4; k++) {
        float w0 = wjk[0][k], w1 = wjk[1][k], w2 = wjk[2][k], w3 = wjk[3][k];
        float wp[10];
        wp[0] = w0 * w0;        wp[1] = 2.f * w0 * w1; wp[2] = 2.f * w0 * w2;
        wp[3] = 2.f * w0 * w3;  wp[4] = w1 * w1;       wp[5] = 2.f * w1 * w2;
        wp[6] = 2.f * w1 * w3;  wp[7] = w2 * w2;       wp[8] = 2.f * w2 * w3;
        wp[9] = w3 * w3;
#pragma unroll
        for (int i = 0; i < 4; i++) {
            const float* Ai = A1 + i * 4;
            const float* Gi = G + i * 10;
            m1[i * 4 + k] = Ai[0] * w0 + Ai[1] * w1 + Ai[2] * w2 + Ai[3] * w3;
            float s = Gi[0] * wp[0] + Gi[1] * wp[1] + Gi[2] * wp[2] + Gi[3] * wp[3] +
                      Gi[4] * wp[4] + Gi[5] * wp[5] + Gi[6] * wp[6] + Gi[7] * wp[7] +
                      Gi[8] * wp[8] + Gi[9] * wp[9];
            s2[i * 4 + k] = s;
        }
    }
    m1[0] += s_acr;
    s2[0] += s_acr2 + 2.f * (Xr[0] * wjk[0][0] + Xr[1] * wjk[1][0] +
                             Xr[2] * wjk[2][0] + Xr[3] * wjk[3][0]);
    m1[1] += s_acc;
    s2[1] += s_acc2 + 2.f * (Xc[0] * wjk[0][1] + Xc[1] * wjk[1][1] +
                             Xc[2] * wjk[2][1] + Xc[3] * wjk[3][1]);

    float val[32];
#pragma unroll
    for (int L = 0; L < 16; L++) {
        int h = (L >> 1) + (L & 1) * 8;
        val[L] = m1[h];
        val[16 + L] = s2[h];
    }
    float r = bfly32_full(val, lane) * 0.1f;
    float s0 = warp_red(s_a);
    float* gp = &g_partials[(size_t)((b * OO + o) * NBLK + 0) * 36];
    gp[lane] = r;
    if (lane == 0) gp[32] = s0 * 0.1f;
}

// ===================== EM iterations 1,2: 2 items per thread =====================
__global__ void __launch_bounds__(256, 2) em_pass_kernel(const float* __restrict__ pose,
                                                         const float* __restrict__ act,
                                                         const float* __restrict__ w) {
    __shared__ __align__(16) float4 w_s4[OO * 4 * 32];  // [r=o*4+j][c], 20KB
    __shared__ __align__(16) float p_s[OO * 40];        // per o: 8x float4 {c1lo,c1hi,hvlo,hvhi}, c0 at 32
    __shared__ float red_s[NW][OO][32];
    __shared__ float red0_s[NW][16];

    const int b = blockIdx.y, nb = blockIdx.x;
    const int tid = threadIdx.x, lane = tid & 31, wid = tid >> 5;

    const float4* wg4 = reinterpret_cast<const float4*>(w);
    for (int idx = tid; idx < CC * 40; idx += 256) {
        int ci = idx / 40, r = idx % 40;
        w_s4[r * 32 + ci] = wg4[idx];
    }
    for (int idx = tid; idx < OO * 40; idx += 256) {
        int o = idx / 40, t = idx % 40;
        const int pbase = (b * OO + o) * 40;
        float v;
        if (t < 32) v = g_params[pbase + ((t & 2) ? 16 : 0) + 2 * (t >> 2) + (t & 1)];
        else if (t == 32) v = g_params[pbase + 32];
        else v = 0.f;
        p_s[idx] = v;
    }
    __syncthreads();

    // Two items per thread: n0 = nb*512 + tid, n1 = n0 + 256 (lane == c for both)
    const int c = lane;
    u64 P2a[8], P2b[8];
    u64 cp0a, cp1a, cp0b, cp1b;
    float a0, a1;
    {
        int n0 = nb * 512 + tid;
        bool v0 = n0 < NN;
        int nn0 = v0 ? n0 : (NN - 1);
        int ns = nn0 >> 5;
        const float4* pp = reinterpret_cast<const float4*>(pose) +
                           (size_t)((b * NSP + ns) * CC + c) * 4;
        float4 R0 = pp[0], R1 = pp[1], R2 = pp[2], R3 = pp[3];
        a0 = v0 ? act[(size_t)b * NN + n0] : 0.f;
        cp0a = pk((ns / SS + 0.5f) * (1.f / SS), 0.f);
        cp1a = pk((ns % SS + 0.5f) * (1.f / SS), 0.f);
        P2a[0] = pk(R0.x, R2.x); P2a[1] = pk(R0.y, R2.y);
        P2a[2] = pk(R0.z, R2.z); P2a[3] = pk(R0.w, R2.w);
        P2a[4] = pk(R1.x, R3.x); P2a[5] = pk(R1.y, R3.y);
        P2a[6] = pk(R1.z, R3.z); P2a[7] = pk(R1.w, R3.w);
    }
    {
        int n1 = nb * 512 + 256 + tid;
        bool v1 = n1 < NN;
        int nn1 = v1 ? n1 : (NN - 1);
        int ns = nn1 >> 5;
        const float4* pp = reinterpret_cast<const float4*>(pose) +
                           (size_t)((b * NSP + ns) * CC + c) * 4;
        float4 R0 = pp[0], R1 = pp[1], R2 = pp[2], R3 = pp[3];
        a1 = v1 ? act[(size_t)b * NN + n1] : 0.f;
        cp0b = pk((ns / SS + 0.5f) * (1.f / SS), 0.f);
        cp1b = pk((ns % SS + 0.5f) * (1.f / SS), 0.f);
        P2b[0] = pk(R0.x, R2.x); P2b[1] = pk(R0.y, R2.y);
        P2b[2] = pk(R0.z, R2.z); P2b[3] = pk(R0.w, R2.w);
        P2b[4] = pk(R1.x, R3.x); P2b[5] = pk(R1.y, R3.y);
        P2b[6] = pk(R1.z, R3.z); P2b[7] = pk(R1.w, R3.w);
    }

    // votes for both items; w loaded once, serves both
    auto votes2 = [&](int o, u64 va[8], u64 vb[8]) {
        const float4* wp = w_s4 + (o * 4) * 32 + c;
        {
            float4 W = wp[0];
            u64 w0 = pkd(W.x), w1 = pkd(W.y), w2 = pkd(W.z), w3 = pkd(W.w);
            va[0] = f2mul(P2a[0], w0); va[1] = f2mul(P2a[0], w1);
            va[2] = f2mul(P2a[0], w2); va[3] = f2mul(P2a[0], w3);
            va[4] = f2mul(P2a[4], w0); va[5] = f2mul(P2a[4], w1);
            va[6] = f2mul(P2a[4], w2); va[7] = f2mul(P2a[4], w3);
            vb[0] = f2mul(P2b[0], w0); vb[1] = f2mul(P2b[0], w1);
            vb[2] = f2mul(P2b[0], w2); vb[3] = f2mul(P2b[0], w3);
            vb[4] = f2mul(P2b[4], w0); vb[5] = f2mul(P2b[4], w1);
            vb[6] = f2mul(P2b[4], w2); vb[7] = f2mul(P2b[4], w3);
        }
#pragma unroll
        for (int j = 1; j < 4; j++) {
            float4 W = wp[j * 32];
            u64 w0 = pkd(W.x), w1 = pkd(W.y), w2 = pkd(W.z), w3 = pkd(W.w);
            va[0] = f2fma(P2a[j], w0, va[0]); va[1] = f2fma(P2a[j], w1, va[1]);
            va[2] = f2fma(P2a[j], w2, va[2]); va[3] = f2fma(P2a[j], w3, va[3]);
            va[4] = f2fma(P2a[4 + j], w0, va[4]); va[5] = f2fma(P2a[4 + j], w1, va[5]);
            va[6] = f2fma(P2a[4 + j], w2, va[6]); va[7] = f2fma(P2a[4 + j], w3, va[7]);
            vb[0] = f2fma(P2b[j], w0, vb[0]); vb[1] = f2fma(P2b[j], w1, vb[1]);
            vb[2] = f2fma(P2b[j], w2, vb[2]); vb[3] = f2fma(P2b[j], w3, vb[3]);
            vb[4] = f2fma(P2b[4 + j], w0, vb[4]); vb[5] = f2fma(P2b[4 + j], w1, vb[5]);
            vb[6] = f2fma(P2b[4 + j], w2, vb[6]); vb[7] = f2fma(P2b[4 + j], w3, vb[7]);
        }
        va[0] = f2add(va[0], cp0a); va[1] = f2add(va[1], cp1a);
        vb[0] = f2add(vb[0], cp0b); vb[1] = f2add(vb[1], cp1b);
    };

    float rp0[OO], rp1[OO];
    // Pass A
#pragma unroll 1
    for (int o = 0; o < OO; o++) {
        u64 va[8], vb[8];
        votes2(o, va, vb);
        const ulonglong2* mp = reinterpret_cast<const ulonglong2*>(p_s + o * 40);
        u64 apa = 0, apb = 0;
#pragma unroll
        for (int q = 0; q < 8; q++) {
            ulonglong2 M = mp[q];  // M.x = c1 pair, M.y = hv pair
            u64 ta = f2fma(M.y, va[q], M.x);
            apa = f2fma(ta, va[q], apa);
            u64 tb = f2fma(M.y, vb[q], M.x);
            apb = f2fma(tb, vb[q], apb);
        }
        float c0 = p_s[o * 40 + 32];
        float l, h;
        upk(apa, l, h);
        rp0[o] = c0 - (l + h);
        upk(apb, l, h);
        rp1[o] = c0 - (l + h);
    }
    // Softmax per item (registers)
    {
        float mx = rp0[0];
#pragma unroll
        for (int o = 1; o < OO; o++) mx = fmaxf(mx, rp0[o]);
        float s = 0.f;
#pragma unroll
        for (int o = 0; o < OO; o++) { rp0[o] = __expf(rp0[o] - mx); s += rp0[o]; }
        float scl = a0 / s;
#pragma unroll
        for (int o = 0; o < OO; o++) rp0[o] *= scl;
    }
    {
        float mx = rp1[0];
#pragma unroll
        for (int o = 1; o < OO; o++) mx = fmaxf(mx, rp1[o]);
        float s = 0.f;
#pragma unroll
        for (int o = 0; o < OO; o++) { rp1[o] = __expf(rp1[o] - mx); s += rp1[o]; }
        float scl = a1 / s;
#pragma unroll
        for (int o = 0; o < OO; o++) rp1[o] *= scl;
    }

    // Pass B: both items folded into registers BEFORE the butterfly
#pragma unroll 1
    for (int o = 0; o < OO; o++) {
        u64 va[8], vb[8];
        votes2(o, va, vb);
        u64 r0p = pkd(rp0[o]), r1p = pkd(rp1[o]);
        float a16[16];
#pragma unroll
        for (int q = 0; q < 8; q++) {
            u64 x0 = f2mul(r0p, va[q]);            // item0 S1 pair
            u64 x1 = f2mul(r1p, vb[q]);            // item1 S1 pair
            u64 t1 = f2add(x0, x1);                // combined S1
            u64 t2 = f2fma(x1, vb[q], f2mul(x0, va[q]));  // combined S2
            float s1l, s1h, s2l, s2h;
            upk(t1, s1l, s1h);
            upk(t2, s2l, s2h);
            float ml = (lane & 16) ? s2l : s1l;
            float gl = (lane & 16) ? s1l : s2l;
            a16[2 * q] = ml + __shfl_xor_sync(0xffffffffu, gl, 16);
            float mh = (lane & 16) ? s2h : s1h;
            float gh = (lane & 16) ? s1h : s2h;
            a16[2 * q + 1] = mh + __shfl_xor_sync(0xffffffffu, gh, 16);
        }
        red_s[wid][o][lane] = bfly16_tail(a16, lane);
    }
    {
        float val[16];
#pragma unroll
        for (int i = 0; i < 16; i++) val[i] = (i < OO) ? (rp0[i] + rp1[i]) : 0.f;
        float s0 = bfly16_full(val, lane);
        int o = lane >> 1;
        if (!(lane & 1) && o < OO) red0_s[wid][o] = s0;
    }
    __syncthreads();

    for (int it = tid; it < OO * 33; it += 256) {
        int o = it / 33, t = it % 33;
        float s = 0.f;
#pragma unroll
        for (int wdx = 0; wdx < NW; wdx++)
            s += (t < 32) ? red_s[wdx][o][t] : red0_s[wdx][o];
        g_partials[((b * OO + o) * NBLK + nb) * 36 + t] = s;
    }
}

__global__ void __launch_bounds__(64) finalize_kernel(const float* __restrict__ beta_a,
                                                      const float* __restrict__ beta_v,
                                                      float inv_temp, int is_final, int nblk,
                                                      float* __restrict__ out) {
    __shared__ float sums[36];
    const int o = blockIdx.x, b = blockIdx.y, t = threadIdx.x;
    if (t < 33) {
        const size_t base = (size_t)(b * OO + o) * NBLK * 36;
        float s = 0.f;
        for (int k = 0; k < nblk; k++) s += g_partials[base + k * 36 + t];
        sums[t] = s;
    }
    __syncthreads();
    if (t < 16) {
        const int ip = (t < 8) ? 2 * t : 2 * (t - 8) + 1;
        float S0 = sums[32];
        float S1 = sums[ip], S2 = sums[16 + ip];
        float inv = 1.f / (S0 + EPSV);
        float mean = S1 * inv;
        float raw = S2 - mean * (2.f * S1 - mean * S0);
        float var = fmaxf(raw * inv, 0.f) + EPSV;
        float hv = 0.5f / var;
        float lv = logf(var);
        float hvm2 = hv * mean * mean;
        float lvs = lv, ms = hvm2;
#pragma unroll
        for (int off = 8; off; off >>= 1) {
            lvs += __shfl_down_sync(0x0000ffffu, lvs, off);
            ms += __shfl_down_sync(0x0000ffffu, ms, off);
        }
        const int pbase = (b * OO + o) * 40;
        if (is_final) {
            out[((size_t)b * OO + o) * 16 + t] = mean;
        } else {
            g_params[pbase + ip] = -2.f * hv * mean;   // c1
            g_params[pbase + 16 + ip] = hv;            // hv
        }
        if (t == 0) {
            float bv = beta_v[o], ba = beta_a[o];
            float cost = S0 * fmaf(0.5f, lvs, 16.f * bv);
            float actj = 1.f / (1.f + expf(-inv_temp * (ba - cost)));
            if (is_final) {
                out[(size_t)BB * OO * 16 + b * OO + o] = actj;
            } else {
                g_params[pbase + 32] =
                    logf(actj + EPSV) - 0.5f * (16.f * 1.8378770664093453f + lvs) - ms;
            }
        }
    }
}

extern "C" void kernel_launch(void* const* d_in, const int* in_sizes, int n_in,
                              void* d_out, int out_size) {
    const float* pose = (const float*)d_in[0];
    const float* act  = (const float*)d_in[1];
    const float* w    = (const float*)d_in[2];
    const float* ba   = (const float*)d_in[3];
    const float* bv   = (const float*)d_in[4];
    float* out = (float*)d_out;

    dim3 gp(NBLK, BB);
    dim3 gf(OO, BB);
    // it 0 (factorized)
    first_stats_kernel<<<256, 64>>>(pose, act);
    first_contract_kernel<<<BB, 320>>>(w);
    finalize_kernel<<<gf, 64>>>(ba, bv, 0.0005f, 0, 1, out);
    // it 1
    em_pass_kernel<<<gp, 256>>>(pose, act, w);
    finalize_kernel<<<gf, 64>>>(ba, bv, 0.000975f, 0, NBLK, out);
    // it 2 (final) — launch index 5 = em_pass (ncu -s 5 captures it)
    em_pass_kernel<<<gp, 256>>>(pose, act, w);
    finalize_kernel<<<gf, 64>>>(ba, bv, 0.00142625f, 1, NBLK, out);
}